// round 1
// baseline (speedup 1.0000x reference)
#include <cuda_runtime.h>

#define B_   256
#define T_   250
#define NIN  700
#define NHID 512
#define NOUT 20

// Scratch (static __device__ — no runtime allocation)
__device__ float g_iin[(size_t)B_ * T_ * NHID];      // [B][T][H] input currents, 131 MB
__device__ float g_wint[4 * NIN * NHID];             // interleaved weights [kk=4n+v][h]
__device__ float g_wrecT[NHID * NHID];               // w_rec transposed: [j][h] = w_rec[h][j]

// ---------------------------------------------------------------------------
// Prep: interleave the 4 KAN weight matrices into virtual-K layout.
// g_wint[(4n+v)*512 + h] = Wv[h][n],  v: 0=w_kan, 1=d1, 2=d2, 3=d3
// ---------------------------------------------------------------------------
__global__ void prep_wint_kernel(const float* __restrict__ wk,
                                 const float* __restrict__ d1,
                                 const float* __restrict__ d2,
                                 const float* __restrict__ d3) {
    int i = blockIdx.x * blockDim.x + threadIdx.x;
    if (i >= NHID * NIN) return;
    int h = i % NHID;
    int n = i / NHID;
    g_wint[(4 * n + 0) * NHID + h] = wk[h * NIN + n];
    g_wint[(4 * n + 1) * NHID + h] = d1[h * NIN + n];
    g_wint[(4 * n + 2) * NHID + h] = d2[h * NIN + n];
    g_wint[(4 * n + 3) * NHID + h] = d3[h * NIN + n];
}

__global__ void prep_wrect_kernel(const float* __restrict__ wrec) {
    int i = blockIdx.x * blockDim.x + threadIdx.x;
    if (i >= NHID * NHID) return;
    int h = i % NHID;
    int j = i / NHID;
    g_wrecT[j * NHID + h] = wrec[h * NHID + j];
}

// ---------------------------------------------------------------------------
// GEMM: i_in[m][h] = sum_{kk<2800} A'[m][kk] * g_wint[kk][h]
//   A'[m][4n+v] = variant_v(x[m][n]),  variants: x, t1=min(|x|,1), t1^2, t1^3
// M = B*T = 64000, N = 512, K' = 2800. BM=128 BN=64 BK=16 (175 exact iters).
// ---------------------------------------------------------------------------
#define BM 128
#define BN 64
#define BK 16

__global__ __launch_bounds__(256) void gemm_kernel(const float* __restrict__ x) {
    __shared__ float As[BK][BM];
    __shared__ float Ws[BK][BN];

    const int tid = threadIdx.x;
    const int m0 = blockIdx.y * BM;
    const int n0 = blockIdx.x * BN;
    const int tx = tid & 15;        // output col group (4 cols each)
    const int ty = tid >> 4;        // output row group (8 rows each)

    // A-load mapping: 512 x-values per tile (128 rows x 4 n), 2 per thread
    const int lm = tid >> 1;        // row 0..127
    const int ln = (tid & 1) * 2;   // n offset 0 or 2

    // W-load mapping: 16 rows x 64 cols = 256 float4 loads, 1 per thread
    const int wkr = tid >> 4;       // kk row 0..15
    const int wcc = (tid & 15) * 4; // col

    float acc[8][4];
#pragma unroll
    for (int i = 0; i < 8; i++)
#pragma unroll
        for (int j = 0; j < 4; j++) acc[i][j] = 0.f;

    for (int kb = 0; kb < 175; kb++) {
        const int nbase = kb * 4;
        const float x0 = x[(size_t)(m0 + lm) * NIN + nbase + ln];
        const float x1 = x[(size_t)(m0 + lm) * NIN + nbase + ln + 1];
        const float4 wv =
            *(const float4*)&g_wint[(size_t)(kb * 16 + wkr) * NHID + n0 + wcc];

        __syncthreads();  // previous tile's readers done
        {
            float a0 = fminf(fabsf(x0), 1.f), b0 = a0 * a0, c0 = b0 * a0;
            As[4 * ln + 0][lm] = x0;
            As[4 * ln + 1][lm] = a0;
            As[4 * ln + 2][lm] = b0;
            As[4 * ln + 3][lm] = c0;
            float a1 = fminf(fabsf(x1), 1.f), b1 = a1 * a1, c1 = b1 * a1;
            As[4 * ln + 4][lm] = x1;
            As[4 * ln + 5][lm] = a1;
            As[4 * ln + 6][lm] = b1;
            As[4 * ln + 7][lm] = c1;
            *(float4*)&Ws[wkr][wcc] = wv;
        }
        __syncthreads();

#pragma unroll
        for (int kk = 0; kk < BK; kk++) {
            const float4 a0 = *(const float4*)&As[kk][ty * 8];
            const float4 a1 = *(const float4*)&As[kk][ty * 8 + 4];
            const float4 bb = *(const float4*)&Ws[kk][tx * 4];
            const float av[8] = {a0.x, a0.y, a0.z, a0.w, a1.x, a1.y, a1.z, a1.w};
            const float bv[4] = {bb.x, bb.y, bb.z, bb.w};
#pragma unroll
            for (int i = 0; i < 8; i++)
#pragma unroll
                for (int j = 0; j < 4; j++) acc[i][j] += av[i] * bv[j];
        }
    }

#pragma unroll
    for (int i = 0; i < 8; i++) {
        float4 v = make_float4(acc[i][0], acc[i][1], acc[i][2], acc[i][3]);
        *(float4*)&g_iin[(size_t)(m0 + ty * 8 + i) * NHID + n0 + tx * 4] = v;
    }
}

// ---------------------------------------------------------------------------
// Scan: one CTA per batch element, one thread per hidden unit.
// Recurrent matvec done sparsely over the compacted active-spike list.
// ---------------------------------------------------------------------------
__global__ __launch_bounds__(512) void scan_kernel(const float* __restrict__ w_out,
                                                   float* __restrict__ out) {
    const int b = blockIdx.x;
    const int h = threadIdx.x;
    const int warp = h >> 5;
    const int lane = h & 31;

    __shared__ int s_idx[NHID];         // compacted active spike indices
    __shared__ unsigned s_mask[16];     // per-warp ballot masks

    float v = 0.f, a = 0.f, sprev = 0.f;
    float vout = 0.f, accum = 0.f;      // only meaningful for h < NOUT
    int cnt = 0;                        // active count from previous step

    const float* iin = g_iin + (size_t)b * T_ * NHID + h;
    float cur = iin[0];

    __syncthreads();

    for (int t = 0; t < T_; t++) {
        float i1 = cur;
        if (t + 1 < T_) cur = iin[(size_t)(t + 1) * NHID];  // prefetch next step

        // sparse recurrent input: i1 += sum over active j of w_rec[h][j]
        for (int k = 0; k < cnt; k++) {
            i1 += g_wrecT[s_idx[k] * NHID + h];
        }

        // adaptive LIF (ALPHA=0.95, RHO=0.85, THRESH=1, BETA_A=0.05)
        v = 0.95f * v + 0.05f * i1 - sprev;
        a = 0.85f * a + 0.15f * sprev;
        const float snew = (v - (1.0f + 0.05f * a)) > 0.f ? 1.f : 0.f;

        // deterministic compaction of new spikes
        const unsigned m = __ballot_sync(0xffffffffu, snew != 0.f);
        if (lane == 0) s_mask[warp] = m;
        __syncthreads();  // old s_idx readers done; s_mask visible

        int total = 0, base = 0;
#pragma unroll
        for (int w = 0; w < 16; w++) {
            const int p = __popc(s_mask[w]);
            total += p;
            if (w < warp) base += p;
        }
        if (snew != 0.f) s_idx[base + __popc(m & ((1u << lane) - 1u))] = h;
        __syncthreads();  // new s_idx visible

        // readout LIF (BETA_OUT=0.9, THRESH=1); output collects post-reset v_out
        if (h < NOUT) {
            float io = 0.f;
            for (int k = 0; k < total; k++) io += w_out[h * NHID + s_idx[k]];
            vout = 0.9f * vout + io;
            const float so = (vout - 1.0f) > 0.f ? 1.f : 0.f;
            vout -= so;
            accum += vout;
        }

        sprev = snew;
        cnt = total;
    }

    if (h < NOUT) out[b * NOUT + h] = accum * (1.0f / (float)T_);
}

// ---------------------------------------------------------------------------
extern "C" void kernel_launch(void* const* d_in, const int* in_sizes, int n_in,
                              void* d_out, int out_size) {
    const float* x     = (const float*)d_in[0];
    const float* w_kan = (const float*)d_in[1];
    const float* d1    = (const float*)d_in[2];
    const float* d2    = (const float*)d_in[3];
    const float* d3    = (const float*)d_in[4];
    const float* w_rec = (const float*)d_in[5];
    const float* w_out = (const float*)d_in[6];
    float* out = (float*)d_out;

    prep_wint_kernel<<<(NHID * NIN + 255) / 256, 256>>>(w_kan, d1, d2, d3);
    prep_wrect_kernel<<<(NHID * NHID + 255) / 256, 256>>>(w_rec);

    dim3 grid(NHID / BN, (B_ * T_) / BM);  // (8, 500)
    gemm_kernel<<<grid, 256>>>(x);

    scan_kernel<<<B_, NHID>>>(w_out, out);
}

// round 3
// speedup vs baseline: 5.0037x; 5.0037x over previous
#include <cuda_runtime.h>
#include <cuda_bf16.h>
#include <cstdint>

#define B_   256
#define T_   250
#define NIN  700
#define NHID 512
#define NOUT 20
#define KPAD 2816          // 4*NIN = 2800 padded to 64*44
#define NSTAGE 44          // K stages of 64 bf16

// ---------------- scratch (static __device__, no runtime alloc) -------------
__device__ float         g_iin[(size_t)B_ * T_ * NHID];   // [B*T][H] fp32
__device__ __nv_bfloat16 g_wbf[(size_t)NHID * KPAD];      // [h][kk] bf16, kk=4n+v
__device__ float         g_wrecT[NHID * NHID];            // w_rec^T

// ---------------- prep kernels ----------------------------------------------
__global__ void prep_wbf_kernel(const float* __restrict__ wk, const float* __restrict__ d1,
                                const float* __restrict__ d2, const float* __restrict__ d3) {
    int i = blockIdx.x * blockDim.x + threadIdx.x;
    if (i >= NHID * 704) return;
    int h = i / 704, n = i % 704;
    __nv_bfloat16* dst = &g_wbf[(size_t)h * KPAD + 4 * n];
    if (n < NIN) {
        dst[0] = __float2bfloat16(wk[h * NIN + n]);
        dst[1] = __float2bfloat16(d1[h * NIN + n]);
        dst[2] = __float2bfloat16(d2[h * NIN + n]);
        dst[3] = __float2bfloat16(d3[h * NIN + n]);
    } else {
        dst[0] = dst[1] = dst[2] = dst[3] = __float2bfloat16(0.f);
    }
}
__global__ void prep_wrect_kernel(const float* __restrict__ wrec) {
    int i = blockIdx.x * blockDim.x + threadIdx.x;
    if (i >= NHID * NHID) return;
    int h = i % NHID, j = i / NHID;
    g_wrecT[j * NHID + h] = wrec[h * NHID + j];
}

// ---------------- mma helpers ------------------------------------------------
__device__ __forceinline__ uint32_t smem_u32(const void* p) {
    uint32_t a;
    asm("{ .reg .u64 t; cvta.to.shared.u64 t, %1; cvt.u32.u64 %0, t; }"
        : "=r"(a) : "l"(p));
    return a;
}
__device__ __forceinline__ void ldmx4(uint32_t* r, uint32_t addr) {
    asm volatile("ldmatrix.sync.aligned.m8n8.x4.shared.b16 {%0,%1,%2,%3}, [%4];"
                 : "=r"(r[0]), "=r"(r[1]), "=r"(r[2]), "=r"(r[3]) : "r"(addr));
}
__device__ __forceinline__ void mma16816(float* c, const uint32_t* a, uint32_t b0, uint32_t b1) {
    asm volatile(
        "mma.sync.aligned.m16n8k16.row.col.f32.bf16.bf16.f32 "
        "{%0,%1,%2,%3}, {%4,%5,%6,%7}, {%8,%9}, {%0,%1,%2,%3};"
        : "+f"(c[0]), "+f"(c[1]), "+f"(c[2]), "+f"(c[3])
        : "r"(a[0]), "r"(a[1]), "r"(a[2]), "r"(a[3]), "r"(b0), "r"(b1));
}

// ---------------- GEMM: C[64000,512] = A'[.,KPAD] x B[512,KPAD]^T ------------
// CTA 128x128, 8 warps (2M x 4N), warp tile 64x32, K staged 64 (double buffer).
// SW128 swizzle on 128B rows reduces to: col ^ ((row & 7) << 4).
#define SMEM_A 0                    // 2 x 16384
#define SMEM_B 32768                // 2 x 16384
#define SM_TOT 65536

__global__ __launch_bounds__(256) void gemm_kernel(const float* __restrict__ x) {
    extern __shared__ char sm[];
    const uint32_t smb = smem_u32(sm);
    const int tid = threadIdx.x, lane = tid & 31, wid = tid >> 5;
    const int wm = wid >> 2, wn = wid & 3;
    const int m0 = blockIdx.y * 128, n0 = blockIdx.x * 128;

    // conversion/store mapping: 2 threads per row, 64 kk-bytes each
    const int crow = tid >> 1;
    const int cgrp = tid & 1;                 // 0: n+0..7, 1: n+8..15
    const uint32_t cxor = (uint32_t)((crow & 7) << 4);
    const uint32_t cbase = (uint32_t)(crow * 128 + cgrp * 0);  // col added per store

    // ldmatrix A per-lane geometry
    const int arowL = lane & 15;                          // row within 16
    const uint32_t akhalf = (uint32_t)((lane >> 4) << 4); // k-byte half select
    const uint32_t axor = (uint32_t)((arowL & 7) << 4);
    const uint32_t aoff0 = (uint32_t)((wm * 64 + arowL) * 128);

    // ldmatrix B per-lane geometry
    const int nrowL = (lane & 7) + ((lane >> 4) << 3);
    const uint32_t bkhalf = (uint32_t)(((lane >> 3) & 1) << 4);
    const uint32_t bxor = (uint32_t)((nrowL & 7) << 4);
    const uint32_t boff0 = (uint32_t)((wn * 32 + nrowL) * 128);

    float acc[4][4][4];
#pragma unroll
    for (int i = 0; i < 4; i++)
#pragma unroll
        for (int j = 0; j < 4; j++)
#pragma unroll
            for (int q = 0; q < 4; q++) acc[i][j][q] = 0.f;

    float xs[8];
    uint4 wv[4];

    // ---- stage loaders -----------------------------------------------------
    auto load_stage = [&](int kb) {
        const int nb = kb * 16 + cgrp * 8;
        if (nb + 8 <= NIN) {
            float4 v0 = __ldg((const float4*)(x + (size_t)(m0 + crow) * NIN + nb));
            float4 v1 = __ldg((const float4*)(x + (size_t)(m0 + crow) * NIN + nb + 4));
            xs[0] = v0.x; xs[1] = v0.y; xs[2] = v0.z; xs[3] = v0.w;
            xs[4] = v1.x; xs[5] = v1.y; xs[6] = v1.z; xs[7] = v1.w;
        } else {
#pragma unroll
            for (int j = 0; j < 8; j++)
                xs[j] = (nb + j < NIN) ? x[(size_t)(m0 + crow) * NIN + nb + j] : 0.f;
        }
        const char* wsrc = (const char*)g_wbf + (size_t)(n0 + crow) * (KPAD * 2)
                           + kb * 128 + cgrp * 64;
#pragma unroll
        for (int j = 0; j < 4; j++) wv[j] = __ldg((const uint4*)(wsrc + j * 16));
    };
    auto store_stage = [&](int slot) {
        char* ab = sm + SMEM_A + slot * 16384;
        char* bb = sm + SMEM_B + slot * 16384;
        uint32_t p[16];
#pragma unroll
        for (int j = 0; j < 8; j++) {
            float t1 = fminf(fabsf(xs[j]), 1.f);
            float t2 = t1 * t1, t3 = t2 * t1;
            __nv_bfloat162 a = __floats2bfloat162_rn(xs[j], t1);
            __nv_bfloat162 b = __floats2bfloat162_rn(t2, t3);
            p[2 * j]     = *(uint32_t*)&a;
            p[2 * j + 1] = *(uint32_t*)&b;
        }
#pragma unroll
        for (int j = 0; j < 4; j++) {
            uint32_t col = (uint32_t)(cgrp * 64 + j * 16);
            *(uint4*)(ab + crow * 128 + (col ^ cxor)) =
                make_uint4(p[4 * j], p[4 * j + 1], p[4 * j + 2], p[4 * j + 3]);
            *(uint4*)(bb + crow * 128 + (col ^ cxor)) = wv[j];
        }
    };

    load_stage(0);
    store_stage(0);

    for (int k = 0; k < NSTAGE; k++) {
        __syncthreads();
        const int p = k & 1;
        const bool hn = (k + 1 < NSTAGE);
        if (hn) load_stage(k + 1);

        const uint32_t abuf = smb + SMEM_A + p * 16384;
        const uint32_t bbuf = smb + SMEM_B + p * 16384;
#pragma unroll
        for (int ks = 0; ks < 4; ks++) {
            uint32_t af[4][4], bf[2][4];
            const uint32_t aklow = ((uint32_t)(ks * 32) + akhalf) ^ axor;
#pragma unroll
            for (int mt = 0; mt < 4; mt++)
                ldmx4(af[mt], abuf + aoff0 + (uint32_t)(mt * 2048) + aklow);
            const uint32_t bklow = ((uint32_t)(ks * 32) + bkhalf) ^ bxor;
#pragma unroll
            for (int q = 0; q < 2; q++)
                ldmx4(bf[q], bbuf + boff0 + (uint32_t)(q * 2048) + bklow);
#pragma unroll
            for (int mt = 0; mt < 4; mt++)
#pragma unroll
                for (int nt = 0; nt < 4; nt++)
                    mma16816(acc[mt][nt], af[mt],
                             bf[nt >> 1][2 * (nt & 1)], bf[nt >> 1][2 * (nt & 1) + 1]);
        }
        if (hn) store_stage(p ^ 1);
    }

    // ---- epilogue ----------------------------------------------------------
#pragma unroll
    for (int mt = 0; mt < 4; mt++) {
        const int r0 = m0 + wm * 64 + mt * 16 + (lane >> 2);
#pragma unroll
        for (int nt = 0; nt < 4; nt++) {
            const int col = n0 + wn * 32 + nt * 8 + 2 * (lane & 3);
            *(float2*)&g_iin[(size_t)r0 * NHID + col] =
                make_float2(acc[mt][nt][0], acc[mt][nt][1]);
            *(float2*)&g_iin[(size_t)(r0 + 8) * NHID + col] =
                make_float2(acc[mt][nt][2], acc[mt][nt][3]);
        }
    }
}

// ---------------- scan: 1 CTA / batch, 1 thread / hidden unit ---------------
__global__ __launch_bounds__(512) void scan_kernel(const float* __restrict__ w_out,
                                                   float* __restrict__ out) {
    const int b = blockIdx.x, h = threadIdx.x;
    const int warp = h >> 5, lane = h & 31;
    __shared__ int s_idx[NHID];
    __shared__ unsigned s_mask[16];

    float v = 0.f, a = 0.f, sprev = 0.f, vout = 0.f, accum = 0.f;
    int cnt = 0;
    const float* iin = g_iin + (size_t)b * T_ * NHID + h;
    float c0 = iin[0], c1 = iin[NHID], c2 = iin[2 * NHID], c3 = iin[3 * NHID];

    for (int t = 0; t < T_; t++) {
        float i1 = c0;
        c0 = c1; c1 = c2; c2 = c3;
        c3 = (t + 4 < T_) ? iin[(size_t)(t + 4) * NHID] : 0.f;

        for (int k = 0; k < cnt; k++) i1 += g_wrecT[s_idx[k] * NHID + h];

        v = 0.95f * v + 0.05f * i1 - sprev;
        a = 0.85f * a + 0.15f * sprev;
        const bool spk = (v - (1.0f + 0.05f * a)) > 0.f;

        const int total = __syncthreads_count((int)spk);
        if (total) {  // rare path: deterministic compaction
            const unsigned m = __ballot_sync(0xffffffffu, spk);
            if (lane == 0) s_mask[warp] = m;
            __syncthreads();
            int base = 0;
#pragma unroll
            for (int w = 0; w < 16; w++)
                if (w < warp) base += __popc(s_mask[w]);
            if (spk) s_idx[base + __popc(m & ((1u << lane) - 1u))] = h;
            __syncthreads();
        }

        if (h < NOUT) {
            float io = 0.f;
            for (int k = 0; k < total; k++) io += w_out[h * NHID + s_idx[k]];
            vout = 0.9f * vout + io;
            const float so = vout > 1.f ? 1.f : 0.f;
            vout -= so;
            accum += vout;
        }
        sprev = spk ? 1.f : 0.f;
        cnt = total;
    }
    if (h < NOUT) out[b * NOUT + h] = accum * (1.0f / (float)T_);
}

// ---------------------------------------------------------------------------
extern "C" void kernel_launch(void* const* d_in, const int* in_sizes, int n_in,
                              void* d_out, int out_size) {
    const float* x     = (const float*)d_in[0];
    const float* w_kan = (const float*)d_in[1];
    const float* d1    = (const float*)d_in[2];
    const float* d2    = (const float*)d_in[3];
    const float* d3    = (const float*)d_in[4];
    const float* w_rec = (const float*)d_in[5];
    const float* w_out = (const float*)d_in[6];
    float* out = (float*)d_out;

    cudaFuncSetAttribute(gemm_kernel, cudaFuncAttributeMaxDynamicSharedMemorySize, SM_TOT);

    prep_wbf_kernel<<<(NHID * 704 + 255) / 256, 256>>>(w_kan, d1, d2, d3);
    prep_wrect_kernel<<<(NHID * NHID + 255) / 256, 256>>>(w_rec);

    dim3 grid(NHID / 128, (B_ * T_) / 128);  // (4, 500)
    gemm_kernel<<<grid, 256, SM_TOT>>>(x);

    scan_kernel<<<B_, NHID>>>(w_out, out);
}

// round 5
// speedup vs baseline: 5.2164x; 1.0425x over previous
#include <cuda_runtime.h>
#include <cuda_bf16.h>
#include <cstdint>

#define B_   256
#define T_   250
#define NIN  700
#define NHID 512
#define NOUT 20
#define KPAD 2816          // 4*NIN = 2800 padded to 128*22 (fp8 bytes)
#define NSTG 22            // K stages of 128 bytes
#define WSCALE 64.0f       // weight pre-scale into e4m3 normal range

// ---------------- scratch (static __device__, no runtime alloc) -------------
__device__ float   g_iin[(size_t)B_ * T_ * NHID];   // [B*T][H] fp32
__device__ uint8_t g_w8[(size_t)NHID * KPAD];       // [h][kk] e4m3, kk=4n+v
__device__ float   g_wrecT[NHID * NHID];            // w_rec^T

// ---------------- helpers ----------------------------------------------------
__device__ __forceinline__ uint32_t smem_u32(const void* p) {
    uint32_t a;
    asm("{ .reg .u64 t; cvta.to.shared.u64 t, %1; cvt.u32.u64 %0, t; }"
        : "=r"(a) : "l"(p));
    return a;
}
__device__ __forceinline__ uint32_t pack_e4m3_4(float f0, float f1, float f2, float f3) {
    uint16_t lo, hi;  // d<7:0> = cvt(src2), d<15:8> = cvt(src1)
    asm("cvt.rn.satfinite.e4m3x2.f32 %0, %1, %2;" : "=h"(lo) : "f"(f1), "f"(f0));
    asm("cvt.rn.satfinite.e4m3x2.f32 %0, %1, %2;" : "=h"(hi) : "f"(f3), "f"(f2));
    return (uint32_t)lo | ((uint32_t)hi << 16);   // bytes f0,f1,f2,f3 (k-ascending)
}
__device__ __forceinline__ void ldmx4(uint32_t* r, uint32_t addr) {
    asm volatile("ldmatrix.sync.aligned.m8n8.x4.shared.b16 {%0,%1,%2,%3}, [%4];"
                 : "=r"(r[0]), "=r"(r[1]), "=r"(r[2]), "=r"(r[3]) : "r"(addr));
}
__device__ __forceinline__ void mma_e4m3(float* c, const uint32_t* a,
                                         uint32_t b0, uint32_t b1) {
    asm volatile(
        "mma.sync.aligned.m16n8k32.row.col.f32.e4m3.e4m3.f32 "
        "{%0,%1,%2,%3}, {%4,%5,%6,%7}, {%8,%9}, {%0,%1,%2,%3};"
        : "+f"(c[0]), "+f"(c[1]), "+f"(c[2]), "+f"(c[3])
        : "r"(a[0]), "r"(a[1]), "r"(a[2]), "r"(a[3]), "r"(b0), "r"(b1));
}

// ---------------- prep kernels ----------------------------------------------
__global__ void prep_w8_kernel(const float* __restrict__ wk, const float* __restrict__ d1,
                               const float* __restrict__ d2, const float* __restrict__ d3) {
    int i = blockIdx.x * blockDim.x + threadIdx.x;
    if (i >= NHID * 704) return;
    int h = i / 704, n = i % 704;
    uint32_t w = 0;
    if (n < NIN)
        w = pack_e4m3_4(wk[h * NIN + n] * WSCALE, d1[h * NIN + n] * WSCALE,
                        d2[h * NIN + n] * WSCALE, d3[h * NIN + n] * WSCALE);
    *(uint32_t*)&g_w8[(size_t)h * KPAD + 4 * n] = w;
}
__global__ void prep_wrect_kernel(const float* __restrict__ wrec) {
    int i = blockIdx.x * blockDim.x + threadIdx.x;
    if (i >= NHID * NHID) return;
    int h = i % NHID, j = i / NHID;
    g_wrecT[j * NHID + h] = wrec[h * NHID + j];
}

// ---------------- GEMM: C[64000,512] = A'[.,KPAD] x B[512,KPAD]^T (e4m3) ----
// CTA 128x128, 8 warps (2M x 4N), warp tile 64x32. K staged 128 B, dbl-buffered.
// 128B rows => SW128 swizzle reduces to col ^ ((row & 7) << 4).
#define SMEM_A 0                    // 2 x 16384
#define SMEM_B 32768                // 2 x 16384
#define SM_TOT 65536

__global__ __launch_bounds__(256) void gemm_kernel(const float* __restrict__ x) {
    extern __shared__ char sm[];
    const uint32_t smb = smem_u32(sm);
    const int tid = threadIdx.x, lane = tid & 31, wid = tid >> 5;
    const int wm = wid >> 2, wn = wid & 3;
    const int m0 = blockIdx.y * 128, n0 = blockIdx.x * 128;

    // conversion/copy mapping: 2 threads per row, 64 kk-bytes each
    const int crow = tid >> 1;
    const int cgrp = tid & 1;
    const uint32_t cxor = (uint32_t)((crow & 7) << 4);

    // ldmatrix lane geometry (16-row x 32-byte blocks, 4 m8n8.b16 tiles)
    const int lrow = (lane & 7) | (((lane >> 3) & 1) << 3);   // 0..15
    const uint32_t lcolh = (uint32_t)((lane >> 4) << 4);      // 0 or 16
    const uint32_t lxor = (uint32_t)((lrow & 7) << 4);
    const uint32_t aoff0 = (uint32_t)((wm * 64 + lrow) * 128);
    const uint32_t boff0 = (uint32_t)((wn * 32 + lrow) * 128);

    float acc[4][4][4];
#pragma unroll
    for (int i = 0; i < 4; i++)
#pragma unroll
        for (int j = 0; j < 4; j++)
#pragma unroll
            for (int q = 0; q < 4; q++) acc[i][j][q] = 0.f;

    float xs[16];
    uint4 wv[4];

    auto load_stage = [&](int kb) {
        const int nb = kb * 32 + cgrp * 16;
#pragma unroll
        for (int jj = 0; jj < 4; jj++) {
            const int nb4 = nb + 4 * jj;
            if (nb4 + 4 <= NIN) {
                float4 v = __ldg((const float4*)(x + (size_t)(m0 + crow) * NIN + nb4));
                xs[4 * jj] = v.x; xs[4 * jj + 1] = v.y;
                xs[4 * jj + 2] = v.z; xs[4 * jj + 3] = v.w;
            } else {
                xs[4 * jj] = xs[4 * jj + 1] = xs[4 * jj + 2] = xs[4 * jj + 3] = 0.f;
            }
        }
        const uint8_t* wsrc = g_w8 + (size_t)(n0 + crow) * KPAD + kb * 128 + cgrp * 64;
#pragma unroll
        for (int j = 0; j < 4; j++) wv[j] = __ldg((const uint4*)(wsrc + j * 16));
    };
    auto store_stage = [&](int slot) {
        char* ab = sm + SMEM_A + slot * 16384;
        char* bb = sm + SMEM_B + slot * 16384;
        uint32_t p[16];
#pragma unroll
        for (int i = 0; i < 16; i++) {
            float f = xs[i];
            float t1 = fminf(fabsf(f), 1.f);
            float t2 = t1 * t1, t3 = t2 * t1;
            p[i] = pack_e4m3_4(f, t1, t2, t3);
        }
#pragma unroll
        for (int j = 0; j < 4; j++) {
            uint32_t col = (uint32_t)(cgrp * 64 + j * 16);
            *(uint4*)(ab + crow * 128 + (col ^ cxor)) =
                make_uint4(p[4 * j], p[4 * j + 1], p[4 * j + 2], p[4 * j + 3]);
            *(uint4*)(bb + crow * 128 + (col ^ cxor)) = wv[j];
        }
    };

    load_stage(0);
    store_stage(0);

    for (int k = 0; k < NSTG; k++) {
        __syncthreads();
        const int p = k & 1;
        const bool hn = (k + 1 < NSTG);
        if (hn) load_stage(k + 1);

        const uint32_t abuf = smb + SMEM_A + p * 16384;
        const uint32_t bbuf = smb + SMEM_B + p * 16384;
#pragma unroll
        for (int ks = 0; ks < 4; ks++) {
            uint32_t af[4][4], bf[2][4];
            const uint32_t klow = ((uint32_t)(ks * 32) + lcolh) ^ lxor;
#pragma unroll
            for (int mt = 0; mt < 4; mt++)
                ldmx4(af[mt], abuf + aoff0 + (uint32_t)(mt * 2048) + klow);
#pragma unroll
            for (int q = 0; q < 2; q++)
                ldmx4(bf[q], bbuf + boff0 + (uint32_t)(q * 2048) + klow);
            // bf[q]: r0=b0(n-grp0) r1=b0(n-grp1) r2=b1(n-grp0) r3=b1(n-grp1)
#pragma unroll
            for (int mt = 0; mt < 4; mt++)
#pragma unroll
                for (int nt = 0; nt < 4; nt++)
                    mma_e4m3(acc[mt][nt], af[mt],
                             bf[nt >> 1][nt & 1], bf[nt >> 1][(nt & 1) + 2]);
        }
        if (hn) store_stage(p ^ 1);
    }

    // ---- epilogue (undo weight pre-scale) ----------------------------------
    const float inv = 1.0f / WSCALE;
#pragma unroll
    for (int mt = 0; mt < 4; mt++) {
        const int r0 = m0 + wm * 64 + mt * 16 + (lane >> 2);
#pragma unroll
        for (int nt = 0; nt < 4; nt++) {
            const int col = n0 + wn * 32 + nt * 8 + 2 * (lane & 3);
            *(float2*)&g_iin[(size_t)r0 * NHID + col] =
                make_float2(acc[mt][nt][0] * inv, acc[mt][nt][1] * inv);
            *(float2*)&g_iin[(size_t)(r0 + 8) * NHID + col] =
                make_float2(acc[mt][nt][2] * inv, acc[mt][nt][3] * inv);
        }
    }
}

// ---------------- scan: 1 CTA / batch, 1 thread / hidden unit ---------------
__global__ __launch_bounds__(512) void scan_kernel(const float* __restrict__ w_out,
                                                   float* __restrict__ out) {
    const int b = blockIdx.x, h = threadIdx.x;
    const int warp = h >> 5, lane = h & 31;
    __shared__ int s_idx[NHID];
    __shared__ unsigned s_mask[16];

    float v = 0.f, a = 0.f, sprev = 0.f, vout = 0.f, accum = 0.f;
    int cnt = 0;
    const float* iin = g_iin + (size_t)b * T_ * NHID + h;
    float c[8];
#pragma unroll
    for (int j = 0; j < 8; j++) c[j] = iin[(size_t)j * NHID];

#pragma unroll 8
    for (int t = 0; t < T_; t++) {
        float i1 = c[0];
#pragma unroll
        for (int j = 0; j < 7; j++) c[j] = c[j + 1];
        c[7] = (t + 8 < T_) ? iin[(size_t)(t + 8) * NHID] : 0.f;

        for (int k = 0; k < cnt; k++) i1 += g_wrecT[s_idx[k] * NHID + h];

        v = 0.95f * v + 0.05f * i1 - sprev;
        a = 0.85f * a + 0.15f * sprev;
        const bool spk = (v - (1.0f + 0.05f * a)) > 0.f;

        const int total = __syncthreads_count((int)spk);
        if (total) {  // rare path: deterministic compaction
            const unsigned m = __ballot_sync(0xffffffffu, spk);
            if (lane == 0) s_mask[warp] = m;
            __syncthreads();
            int base = 0;
#pragma unroll
            for (int w = 0; w < 16; w++)
                if (w < warp) base += __popc(s_mask[w]);
            if (spk) s_idx[base + __popc(m & ((1u << lane) - 1u))] = h;
            __syncthreads();
        }

        if (h < NOUT) {
            float io = 0.f;
            for (int k = 0; k < total; k++) io += w_out[h * NHID + s_idx[k]];
            vout = 0.9f * vout + io;
            const float so = vout > 1.f ? 1.f : 0.f;
            vout -= so;
            accum += vout;
        }
        sprev = spk ? 1.f : 0.f;
        cnt = total;
    }
    if (h < NOUT) out[b * NOUT + h] = accum * (1.0f / (float)T_);
}

// ---------------------------------------------------------------------------
extern "C" void kernel_launch(void* const* d_in, const int* in_sizes, int n_in,
                              void* d_out, int out_size) {
    const float* x     = (const float*)d_in[0];
    const float* w_kan = (const float*)d_in[1];
    const float* d1    = (const float*)d_in[2];
    const float* d2    = (const float*)d_in[3];
    const float* d3    = (const float*)d_in[4];
    const float* w_rec = (const float*)d_in[5];
    const float* w_out = (const float*)d_in[6];
    float* out = (float*)d_out;

    cudaFuncSetAttribute(gemm_kernel, cudaFuncAttributeMaxDynamicSharedMemorySize, SM_TOT);

    prep_w8_kernel<<<(NHID * 704 + 255) / 256, 256>>>(w_kan, d1, d2, d3);
    prep_wrect_kernel<<<(NHID * NHID + 255) / 256, 256>>>(w_rec);

    dim3 grid(NHID / 128, (B_ * T_) / 128);  // (4, 500)
    gemm_kernel<<<grid, 256, SM_TOT>>>(x);

    scan_kernel<<<B_, NHID>>>(w_out, out);
}